// round 12
// baseline (speedup 1.0000x reference)
#include <cuda_runtime.h>

// RGBuvHistBlock: x [8,3,256,256] f32 in [0,1]; bin_vals [64] = linspace(-1,1).
// hist[nc][b] = sum_p exp(-((2x-1)-b)^2/(2*0.02^2)), normalized per nc.
//
// R12: R11 structure (float2-paired 8-bin window, 4 LDS.64 + 4 STS.64 + 2 EX2
// per pixel; float4 rotated reduce; SPLITS=16 = 384 blocks) with NT=256:
// same block count and same per-SM work, 2x warps/SMSP (5.2) to hide the
// ~8k cyc of exposed LDS latency. Hist becomes 64KB -> dynamic smem.
// Accumulation folded into FMA (h = fma(g, r^j*C_j, h)).

#define NC_TOTAL   24
#define PIX_PER_NC 65536
#define HB         64
#define SPLITS     16
#define CHUNK      4096
#define NT         256
#define NPAIR      32                     // 64 bins as 32 float2 pairs

#define SA    42.46608994f                // sqrt(1250*log2e)
#define SA2   84.93217988f
#define DS    1.34812984f                 // scaled bin spacing
#define TWO_D 2.69625968f
// c_j = 2^{-j^2*DS^2}
#define C1_  0.2837213f
#define C2_  6.479897e-3f
#define C3_  1.191316e-5f
#define C4_  1.763085e-9f
#define C5_  2.100399e-14f
#define C6_  2.014225e-20f
#define C7_  1.554903e-27f

#define SMEM_BYTES (NPAIR * NT * 8)       // 64KB

__device__ float    g_part[NC_TOTAL * SPLITS * HB];
__device__ unsigned g_cnt[NC_TOTAL];

__device__ __forceinline__ float ex2f(float a) {
    float r;
    asm("ex2.approx.ftz.f32 %0, %1;" : "=f"(r) : "f"(a));
    return r;
}

__global__ __launch_bounds__(NT) void hist_fused_kernel(
    const float* __restrict__ x, const float* __restrict__ bin_vals,
    float* __restrict__ out)
{
    extern __shared__ float2 hist2[];      // [NPAIR][NT], 64KB
    __shared__ float2 racc2[NT];           // 8 partials per pair
    __shared__ float  ws[2];
    __shared__ int    slast;

    const int nc    = blockIdx.y;
    const int split = blockIdx.x;
    const int tid   = threadIdx.x;

    // Zero (16 STS.128 per thread).
    {
        float4* hz = reinterpret_cast<float4*>(hist2);
#pragma unroll
        for (int i = 0; i < (NPAIR * NT / 2) / NT; ++i)
            hz[tid + i * NT] = make_float4(0.f, 0.f, 0.f, 0.f);
    }
    __syncthreads();

    const float4* xp = reinterpret_cast<const float4*>(
        x + (size_t)nc * PIX_PER_NC + (size_t)split * CHUNK);

#pragma unroll
    for (int it = 0; it < CHUNK / (4 * NT); ++it) {
        float4 v = xp[tid + it * NT];
        float pv[4] = {v.x, v.y, v.z, v.w};
#pragma unroll
        for (int p = 0; p < 4; ++p) {
            float vf = pv[p];
            float sp = vf * SA2;                       // s' in [0, 2SA]; bin j at j*DS
            int jc   = min(max(__float2int_rn(vf * 63.0f), 3), 60);
            int p0   = (jc - 3) >> 1;                  // window bins [2p0, 2p0+7]
            float ds = fmaf((float)p0, -TWO_D, sp);    // dist to bin 2p0

            float g  = ex2f(-ds * ds);                 // 2^{-ds^2}
            float r  = ex2f(ds * TWO_D);               // 2^{2*DS*ds}
            float r2 = r * r;
            float r3 = r2 * r;
            float r4 = r2 * r2;
            float gr4 = g * r4;                        // overflow-safe grouping

            float2* hp = hist2 + p0 * NT + tid;
            float2 h0 = hp[0 * NT];
            float2 h1 = hp[1 * NT];
            float2 h2 = hp[2 * NT];
            float2 h3 = hp[3 * NT];
            h0.x += g;
            h0.y = fmaf(g,   r  * C1_, h0.y);
            h1.x = fmaf(g,   r2 * C2_, h1.x);
            h1.y = fmaf(g,   r3 * C3_, h1.y);
            h2.x = fmaf(gr4, C4_,      h2.x);
            h2.y = fmaf(gr4, r  * C5_, h2.y);
            h3.x = fmaf(gr4, r2 * C6_, h3.x);
            h3.y = fmaf(gr4, r3 * C7_, h3.y);
            hp[0 * NT] = h0;
            hp[1 * NT] = h1;
            hp[2 * NT] = h2;
            hp[3 * NT] = h3;
        }
    }
    __syncthreads();

    // Reduce phase 1 (float4 view: 4096 float4; pair P = f>>7). Thread
    // (P = tid>>3, eighth j = tid&7) sums 16 float4s, rotated.
    {
        const float4* fv = reinterpret_cast<const float4*>(hist2);
        const int P  = tid >> 3;
        const int jb = (tid & 7) * 16;
        float4 acc = make_float4(0.f, 0.f, 0.f, 0.f);
#pragma unroll
        for (int i = 0; i < 16; ++i) {
            int k = jb + ((i + tid) & 15);
            float4 hv = fv[P * (NT / 2) + k];
            acc.x += hv.x; acc.y += hv.y; acc.z += hv.z; acc.w += hv.w;
        }
        racc2[tid] = make_float2(acc.x + acc.z, acc.y + acc.w);  // (bin 2P, 2P+1)
    }
    __syncthreads();

    // Reduce phase 2: bin b sums its 8 partials.
    if (tid < HB) {
        const int pr = tid >> 1, comp = tid & 1;
        const float* rf = reinterpret_cast<const float*>(racc2);
        float s = 0.0f;
#pragma unroll
        for (int k = 0; k < 8; ++k)
            s += rf[(pr * 8 + k) * 2 + comp];
        g_part[((size_t)nc * SPLITS + split) * HB + tid] = s;
    }
    __syncthreads();

    // Last block per nc reduces + normalizes.
    if (tid == 0) {
        __threadfence();
        unsigned old = atomicAdd(&g_cnt[nc], 1u);
        slast = (old == SPLITS - 1);
    }
    __syncthreads();
    if (!slast) return;
    __threadfence();

    float bsum = 0.0f;
    if (tid < HB) {
        const float* p = g_part + (size_t)nc * SPLITS * HB + tid;
#pragma unroll
        for (int sp = 0; sp < SPLITS; ++sp)
            bsum += p[(size_t)sp * HB];
    }
    float v = (tid < HB) ? bsum : 0.0f;
    float r = v;
#pragma unroll
    for (int o = 16; o; o >>= 1) r += __shfl_xor_sync(0xffffffffu, r, o);
    if (tid == 0)  ws[0] = r;
    if (tid == 32) ws[1] = r;
    __syncthreads();
    float tot = ws[0] + ws[1];

    if (tid < HB)
        out[nc * HB + tid] = v / (tot + 1e-8f);

    if (tid == 0) g_cnt[nc] = 0;   // reset for next graph replay
}

extern "C" void kernel_launch(void* const* d_in, const int* in_sizes, int n_in,
                              void* d_out, int out_size) {
    const float* x        = (const float*)d_in[0];
    const float* bin_vals = (const float*)d_in[1];
    float* out            = (float*)d_out;

    cudaFuncSetAttribute(hist_fused_kernel,
                         cudaFuncAttributeMaxDynamicSharedMemorySize,
                         SMEM_BYTES);

    dim3 grid(SPLITS, NC_TOTAL);
    hist_fused_kernel<<<grid, NT, SMEM_BYTES>>>(x, bin_vals, out);
}

// round 13
// speedup vs baseline: 1.1483x; 1.1483x over previous
#include <cuda_runtime.h>

// RGBuvHistBlock: x [8,3,256,256] f32 in [0,1]; bin_vals [64] = linspace(-1,1).
// hist[nc][b] = sum_p exp(-((2x-1)-b)^2/(2*0.02^2)), normalized per nc.
//
// R13: the ~10.7us plateau across R5/R10/R11/R12 equals input-bytes / 590GB/s:
// DRAM-LATENCY bound (MLP=1: one LDG.128 then ~40 dependent insts). Fix:
// (a) front-batch all 8 LDG.128 per thread -> MLP=8, load streams in ~2us;
// (b) 5-bin window (covers +-2.5 bins; dropped weight <=3.8e-4 -> per-bin err
//     ~8e-5) with 2-EX2 recurrence: 5 LDS.32 + 5 STS.32 per pixel;
// (c) proven skeleton: NT=128, SPLITS=16, static 32KB hist, rotated f4 reduce.

#define NC_TOTAL   24
#define PIX_PER_NC 65536
#define HB         64
#define SPLITS     16
#define CHUNK      4096
#define NT         128
#define NITER      (CHUNK / (4 * NT))    // 8 float4 loads per thread

#define DS    1.34812984f                // scaled bin spacing = sqrt(1250*log2e)*2/63
#define TWO_D 2.69625968f
// C_k = 2^{-k^2*DS^2}
#define C1_  0.2837213f
#define C2_  6.479897e-3f
#define C3_  1.191316e-5f
#define C4_  1.763085e-9f

__device__ float    g_part[NC_TOTAL * SPLITS * HB];
__device__ unsigned g_cnt[NC_TOTAL];

__device__ __forceinline__ float ex2f(float a) {
    float r;
    asm("ex2.approx.ftz.f32 %0, %1;" : "=f"(r) : "f"(a));
    return r;
}

__global__ __launch_bounds__(NT) void hist_fused_kernel(
    const float* __restrict__ x, const float* __restrict__ bin_vals,
    float* __restrict__ out)
{
    const int nc    = blockIdx.y;
    const int split = blockIdx.x;
    const int tid   = threadIdx.x;

    __shared__ float hist[HB * NT];      // 32KB: cell (bin b, thread t) = hist[b*NT+t]
    __shared__ float racc[NT];
    __shared__ float ws[2];
    __shared__ int   slast;

    // Front-batch the block's entire 16KB input: 8 independent LDG.128 (MLP=8).
    const float4* xp = reinterpret_cast<const float4*>(
        x + (size_t)nc * PIX_PER_NC + (size_t)split * CHUNK);
    float4 vin[NITER];
#pragma unroll
    for (int i = 0; i < NITER; ++i)
        vin[i] = xp[tid + i * NT];

    // Zero private hists (16 STS.128 per thread) while loads are in flight.
    {
        float4* hz = reinterpret_cast<float4*>(hist);
#pragma unroll
        for (int i = 0; i < (HB * NT / 4) / NT; ++i)
            hz[tid + i * NT] = make_float4(0.f, 0.f, 0.f, 0.f);
    }
    __syncthreads();

#pragma unroll
    for (int it = 0; it < NITER; ++it) {
        float4 v = vin[it];
        float pv[4] = {v.x, v.y, v.z, v.w};
#pragma unroll
        for (int p = 0; p < 4; ++p) {
            float u  = pv[p] * 63.0f;                    // bin-unit position
            int   j0 = min(max(__float2int_rn(u), 2), 61);
            float cs = (u - (float)(j0 - 2)) * DS;       // scaled dist to leftmost bin

            float A  = ex2f(-cs * cs);                   // 2^{-cs^2}
            float B  = ex2f(cs * TWO_D);                 // 2^{2*DS*cs}
            float B2 = B * B;
            float B3 = B2 * B;
            float B4 = B2 * B2;
            float w0 = A;
            float w1 = A * (B  * C1_);
            float w2 = A * (B2 * C2_);
            float w3 = A * (B3 * C3_);
            float w4 = A * (B4 * C4_);

            float* hp = hist + (j0 - 2) * NT + tid;
            float h0 = hp[0 * NT];
            float h1 = hp[1 * NT];
            float h2 = hp[2 * NT];
            float h3 = hp[3 * NT];
            float h4 = hp[4 * NT];
            hp[0 * NT] = h0 + w0;
            hp[1 * NT] = h1 + w1;
            hp[2 * NT] = h2 + w2;
            hp[3 * NT] = h3 + w3;
            hp[4 * NT] = h4 + w4;
        }
    }
    __syncthreads();

    // Reduce phase 1 (float4 view: 2048 float4, bin b owns f4 idx [b*32, b*32+31]).
    // Thread (b = tid>>1, half = tid&1) sums 16 float4s, rotated: per 8-lane
    // phase the f4 index mod 8 is distinct -> conflict-free.
    {
        const float4* fv = reinterpret_cast<const float4*>(hist);
        const int b = tid >> 1, half = tid & 1;
        float4 acc = make_float4(0.f, 0.f, 0.f, 0.f);
#pragma unroll
        for (int i = 0; i < 16; ++i) {
            int k = b * 32 + half * 16 + ((i + tid) & 15);
            float4 hv = fv[k];
            acc.x += hv.x; acc.y += hv.y; acc.z += hv.z; acc.w += hv.w;
        }
        racc[tid] = (acc.x + acc.y) + (acc.z + acc.w);
    }
    __syncthreads();

    // Reduce phase 2: bin b = racc[2b] + racc[2b+1].
    if (tid < HB)
        g_part[((size_t)nc * SPLITS + split) * HB + tid] =
            racc[2 * tid] + racc[2 * tid + 1];
    __syncthreads();

    // Last block per nc reduces + normalizes.
    if (tid == 0) {
        __threadfence();
        unsigned old = atomicAdd(&g_cnt[nc], 1u);
        slast = (old == SPLITS - 1);
    }
    __syncthreads();
    if (!slast) return;
    __threadfence();

    float bsum = 0.0f;
    if (tid < HB) {
        const float* p = g_part + (size_t)nc * SPLITS * HB + tid;
#pragma unroll
        for (int sp = 0; sp < SPLITS; ++sp)
            bsum += p[(size_t)sp * HB];
    }
    float v = (tid < HB) ? bsum : 0.0f;
    float r = v;
#pragma unroll
    for (int o = 16; o; o >>= 1) r += __shfl_xor_sync(0xffffffffu, r, o);
    if (tid == 0)  ws[0] = r;
    if (tid == 32) ws[1] = r;
    __syncthreads();
    float tot = ws[0] + ws[1];

    if (tid < HB)
        out[nc * HB + tid] = v / (tot + 1e-8f);

    if (tid == 0) g_cnt[nc] = 0;   // reset for next graph replay
}

extern "C" void kernel_launch(void* const* d_in, const int* in_sizes, int n_in,
                              void* d_out, int out_size) {
    const float* x        = (const float*)d_in[0];
    const float* bin_vals = (const float*)d_in[1];
    float* out            = (float*)d_out;

    dim3 grid(SPLITS, NC_TOTAL);
    hist_fused_kernel<<<grid, NT>>>(x, bin_vals, out);
}

// round 14
// speedup vs baseline: 1.1516x; 1.0029x over previous
#include <cuda_runtime.h>

// RGBuvHistBlock: x [8,3,256,256] f32 in [0,1]; bin_vals [64] = linspace(-1,1).
// hist[nc][b] = sum_p exp(-((2x-1)-b)^2/(2*0.02^2)), normalized per nc.
//
// R14 = R13 (front-batched MLP=8 LDG) + 3-pair window:
//   pair-aligned 6-bin window [2p0, 2p0+5] covers >= +-2.5 bins always
//   (same truncation bound as R13's 5-bin), float2 cells ->
//   3 LDS.64 + 3 STS.64 = 6 smem ops/pixel (R13: 10, R11: 8).
//   Weights via 2-EX2 recurrence: w_k = A*B^k*C_k.
// Skeleton: NT=128, SPLITS=16 (384 blocks), static 32KB hist, rotated reduce.

#define NC_TOTAL   24
#define PIX_PER_NC 65536
#define HB         64
#define SPLITS     16
#define CHUNK      4096
#define NT         128
#define NITER      (CHUNK / (4 * NT))    // 8 float4 loads per thread
#define NPAIR      32                    // 64 bins as 32 float2 pairs

#define DS    1.34812984f                // scaled bin spacing = sqrt(1250*log2e)*2/63
#define TWO_D 2.69625968f
// C_k = 2^{-k^2*DS^2}
#define C1_  0.2837213f
#define C2_  6.479897e-3f
#define C3_  1.191316e-5f
#define C4_  1.763085e-9f
#define C5_  2.100399e-14f

__device__ float    g_part[NC_TOTAL * SPLITS * HB];
__device__ unsigned g_cnt[NC_TOTAL];

__device__ __forceinline__ float ex2f(float a) {
    float r;
    asm("ex2.approx.ftz.f32 %0, %1;" : "=f"(r) : "f"(a));
    return r;
}

__global__ __launch_bounds__(NT) void hist_fused_kernel(
    const float* __restrict__ x, const float* __restrict__ bin_vals,
    float* __restrict__ out)
{
    const int nc    = blockIdx.y;
    const int split = blockIdx.x;
    const int tid   = threadIdx.x;

    __shared__ float2 hist2[NPAIR * NT]; // 32KB: pair p, thread t -> hist2[p*NT+t]
    __shared__ float2 racc2[NT];
    __shared__ float  ws[2];
    __shared__ int    slast;

    // Front-batch the block's 16KB input: 8 independent LDG.128 (MLP=8).
    const float4* xp = reinterpret_cast<const float4*>(
        x + (size_t)nc * PIX_PER_NC + (size_t)split * CHUNK);
    float4 vin[NITER];
#pragma unroll
    for (int i = 0; i < NITER; ++i)
        vin[i] = xp[tid + i * NT];

    // Zero hist while loads are in flight (16 STS.128 per thread).
    {
        float4* hz = reinterpret_cast<float4*>(hist2);
#pragma unroll
        for (int i = 0; i < (NPAIR * NT / 2) / NT; ++i)
            hz[tid + i * NT] = make_float4(0.f, 0.f, 0.f, 0.f);
    }
    __syncthreads();

#pragma unroll
    for (int it = 0; it < NITER; ++it) {
        float4 v = vin[it];
        float pv[4] = {v.x, v.y, v.z, v.w};
#pragma unroll
        for (int p = 0; p < 4; ++p) {
            float u  = pv[p] * 63.0f;                   // bin-unit position
            int   jc = min(max(__float2int_rn(u), 2), 61);
            int   p0 = (jc - 2) >> 1;                   // window bins [2p0, 2p0+5]
            float ds = fmaf((float)p0, -TWO_D, u * DS); // scaled dist to bin 2p0

            float A  = ex2f(-ds * ds);                  // 2^{-ds^2}
            float B  = ex2f(ds * TWO_D);                // 2^{2*DS*ds}
            float B2 = B * B;
            float B3 = B2 * B;
            float AB4 = A * (B2 * B2);
            float w0 = A;
            float w1 = A * (B  * C1_);
            float w2 = A * (B2 * C2_);
            float w3 = A * (B3 * C3_);
            float w4 = AB4 * C4_;
            float w5 = AB4 * (B * C5_);

            float2* hp = hist2 + p0 * NT + tid;
            float2 h0 = hp[0 * NT];
            float2 h1 = hp[1 * NT];
            float2 h2 = hp[2 * NT];
            h0.x += w0; h0.y += w1;
            h1.x += w2; h1.y += w3;
            h2.x += w4; h2.y += w5;
            hp[0 * NT] = h0;
            hp[1 * NT] = h1;
            hp[2 * NT] = h2;
        }
    }
    __syncthreads();

    // Reduce phase 1 (float4 view: 2048 float4; pair P owns f4 idx [P*64, P*64+63],
    // each f4 = bins (2P,2P+1) for two adjacent threads). Thread (P=tid>>2,
    // quarter tid&3) sums 16 float4s, rotated to avoid phase conflicts.
    {
        const float4* fv = reinterpret_cast<const float4*>(hist2);
        const int P  = tid >> 2;
        const int jb = (tid & 3) * 16;
        float4 acc = make_float4(0.f, 0.f, 0.f, 0.f);
#pragma unroll
        for (int i = 0; i < 16; ++i) {
            int k = jb + ((i + tid) & 15);
            float4 hv = fv[P * 64 + k];
            acc.x += hv.x; acc.y += hv.y; acc.z += hv.z; acc.w += hv.w;
        }
        racc2[tid] = make_float2(acc.x + acc.z, acc.y + acc.w);  // (bin 2P, 2P+1)
    }
    __syncthreads();

    // Reduce phase 2: bin b sums its 4 partials.
    if (tid < HB) {
        const int pr = tid >> 1, comp = tid & 1;
        const float* rf = reinterpret_cast<const float*>(racc2);
        float s = 0.0f;
#pragma unroll
        for (int k = 0; k < 4; ++k)
            s += rf[(pr * 4 + k) * 2 + comp];
        g_part[((size_t)nc * SPLITS + split) * HB + tid] = s;
    }
    __syncthreads();

    // Last block per nc reduces + normalizes.
    if (tid == 0) {
        __threadfence();
        unsigned old = atomicAdd(&g_cnt[nc], 1u);
        slast = (old == SPLITS - 1);
    }
    __syncthreads();
    if (!slast) return;
    __threadfence();

    float bsum = 0.0f;
    if (tid < HB) {
        const float* p = g_part + (size_t)nc * SPLITS * HB + tid;
#pragma unroll
        for (int sp = 0; sp < SPLITS; ++sp)
            bsum += p[(size_t)sp * HB];
    }
    float v = (tid < HB) ? bsum : 0.0f;
    float r = v;
#pragma unroll
    for (int o = 16; o; o >>= 1) r += __shfl_xor_sync(0xffffffffu, r, o);
    if (tid == 0)  ws[0] = r;
    if (tid == 32) ws[1] = r;
    __syncthreads();
    float tot = ws[0] + ws[1];

    if (tid < HB)
        out[nc * HB + tid] = v / (tot + 1e-8f);

    if (tid == 0) g_cnt[nc] = 0;   // reset for next graph replay
}

extern "C" void kernel_launch(void* const* d_in, const int* in_sizes, int n_in,
                              void* d_out, int out_size) {
    const float* x        = (const float*)d_in[0];
    const float* bin_vals = (const float*)d_in[1];
    float* out            = (float*)d_out;

    dim3 grid(SPLITS, NC_TOTAL);
    hist_fused_kernel<<<grid, NT>>>(x, bin_vals, out);
}

// round 16
// speedup vs baseline: 1.1791x; 1.0239x over previous
#include <cuda_runtime.h>
#include <cstdint>

// RGBuvHistBlock: x [8,3,256,256] f32 in [0,1]; bin_vals [64] = linspace(-1,1).
// hist[nc][b] = sum_p exp(-((2x-1)-b)^2/(2*0.02^2)), normalized per nc.
//
// R16 = R15 with the collision-forwarding SIGN FIXED. b's row k sits at pair
// p0a + d + k (d = p0b - p0a), so it aliases a's row m = d + k:
//   f0 <- na_d   (d in {0,1,2})
//   f1 <- na_{d+1} (d in {-1,0,1})
//   f2 <- na_{d+2} (d in {-2,-1,0})
// R15 used k-d (flipped), dropping a's contribution on real collisions.
// Structure: 6-bin pair window, MLP=8 front-batched LDG, 2-pixel batched RMW,
// asm-pinned LDS/STS order, NT=128, SPLITS=16, rotated float4 reduce.

#define NC_TOTAL   24
#define PIX_PER_NC 65536
#define HB         64
#define SPLITS     16
#define CHUNK      4096
#define NT         128
#define NITER      (CHUNK / (4 * NT))    // 8 float4 loads per thread
#define NPAIR      32
#define ROWB       (NT * 8)              // bytes per pair-row

#define DS    1.34812984f
#define TWO_D 2.69625968f
#define C1_  0.2837213f
#define C2_  6.479897e-3f
#define C3_  1.191316e-5f
#define C4_  1.763085e-9f
#define C5_  2.100399e-14f

__device__ float    g_part[NC_TOTAL * SPLITS * HB];
__device__ unsigned g_cnt[NC_TOTAL];

__device__ __forceinline__ float ex2f(float a) {
    float r;
    asm("ex2.approx.ftz.f32 %0, %1;" : "=f"(r) : "f"(a));
    return r;
}
__device__ __forceinline__ uint32_t smem_u32(const void* p) {
    uint32_t a;
    asm("{ .reg .u64 t; cvta.to.shared.u64 t, %1; cvt.u32.u64 %0, t; }"
        : "=r"(a) : "l"(p));
    return a;
}
#define LDS2(h, addr) \
    asm volatile("ld.shared.v2.f32 {%0,%1}, [%2];" \
                 : "=f"((h).x), "=f"((h).y) : "r"(addr))
#define STS2(addr, v) \
    asm volatile("st.shared.v2.f32 [%0], {%1,%2};" \
                 :: "r"(addr), "f"((v).x), "f"((v).y) : "memory")

__device__ __forceinline__ float2 add2(float2 a, float2 b) {
    return make_float2(a.x + b.x, a.y + b.y);
}

struct PxW { int p0; float2 w0, w1, w2; };

__device__ __forceinline__ PxW px_weights(float vf) {
    PxW r;
    float u  = vf * 63.0f;
    int   jc = min(max(__float2int_rn(u), 2), 61);
    r.p0     = (jc - 2) >> 1;
    float ds = fmaf((float)r.p0, -TWO_D, u * DS);
    float A  = ex2f(-ds * ds);
    float B  = ex2f(ds * TWO_D);
    float B2 = B * B;
    float B3 = B2 * B;
    float AB4 = A * (B2 * B2);
    r.w0 = make_float2(A,              A * (B  * C1_));
    r.w1 = make_float2(A * (B2 * C2_), A * (B3 * C3_));
    r.w2 = make_float2(AB4 * C4_,      AB4 * (B * C5_));
    return r;
}

__global__ __launch_bounds__(NT) void hist_fused_kernel(
    const float* __restrict__ x, const float* __restrict__ bin_vals,
    float* __restrict__ out)
{
    const int nc    = blockIdx.y;
    const int split = blockIdx.x;
    const int tid   = threadIdx.x;

    __shared__ float2 hist2[NPAIR * NT];
    __shared__ float2 racc2[NT];
    __shared__ float  ws[2];
    __shared__ int    slast;

    const uint32_t hbase = smem_u32(hist2) + tid * 8;

    // Front-batch the block's 16KB input: 8 independent LDG.128 (MLP=8).
    const float4* xp = reinterpret_cast<const float4*>(
        x + (size_t)nc * PIX_PER_NC + (size_t)split * CHUNK);
    float4 vin[NITER];
#pragma unroll
    for (int i = 0; i < NITER; ++i)
        vin[i] = xp[tid + i * NT];

    // Zero hist while loads are in flight.
    {
        float4* hz = reinterpret_cast<float4*>(hist2);
#pragma unroll
        for (int i = 0; i < (NPAIR * NT / 2) / NT; ++i)
            hz[tid + i * NT] = make_float4(0.f, 0.f, 0.f, 0.f);
    }
    __syncthreads();

#pragma unroll
    for (int it = 0; it < NITER; ++it) {
        float4 v = vin[it];
        float pa_[2] = {v.x, v.z};
        float pb_[2] = {v.y, v.w};
#pragma unroll
        for (int h = 0; h < 2; ++h) {
            PxW a = px_weights(pa_[h]);
            PxW b = px_weights(pb_[h]);

            uint32_t aa = hbase + (uint32_t)a.p0 * ROWB;
            uint32_t ab = hbase + (uint32_t)b.p0 * ROWB;

            // Batched loads: one exposed LDS latency for both pixels.
            float2 ha0, ha1, ha2, hb0, hb1, hb2;
            LDS2(ha0, aa);
            LDS2(ha1, aa + ROWB);
            LDS2(ha2, aa + 2 * ROWB);
            LDS2(hb0, ab);
            LDS2(hb1, ab + ROWB);
            LDS2(hb2, ab + 2 * ROWB);

            float2 na0 = add2(ha0, a.w0);
            float2 na1 = add2(ha1, a.w1);
            float2 na2 = add2(ha2, a.w2);

            // Collision forwarding (fixed): b row k aliases a row d+k.
            int d = b.p0 - a.p0;
            bool e0 = (d == 0), e1 = (d == 1), e2 = (d == 2);
            bool m1 = (d == -1), m2 = (d == -2);
            float2 f0 = e0 ? na0 : (e1 ? na1 : (e2 ? na2 : hb0));
            float2 f1 = m1 ? na0 : (e0 ? na1 : (e1 ? na2 : hb1));
            float2 f2 = m2 ? na0 : (m1 ? na1 : (e0 ? na2 : hb2));
            f0 = add2(f0, b.w0);
            f1 = add2(f1, b.w1);
            f2 = add2(f2, b.w2);

            // a stores first, then b (b carries forwarded totals on collision).
            STS2(aa, na0);
            STS2(aa + ROWB, na1);
            STS2(aa + 2 * ROWB, na2);
            STS2(ab, f0);
            STS2(ab + ROWB, f1);
            STS2(ab + 2 * ROWB, f2);
        }
    }
    __syncthreads();

    // Reduce phase 1 (float4 view, rotated): pair P = tid>>2, quarter tid&3.
    {
        const float4* fv = reinterpret_cast<const float4*>(hist2);
        const int P  = tid >> 2;
        const int jb = (tid & 3) * 16;
        float4 acc = make_float4(0.f, 0.f, 0.f, 0.f);
#pragma unroll
        for (int i = 0; i < 16; ++i) {
            int k = jb + ((i + tid) & 15);
            float4 hv = fv[P * 64 + k];
            acc.x += hv.x; acc.y += hv.y; acc.z += hv.z; acc.w += hv.w;
        }
        racc2[tid] = make_float2(acc.x + acc.z, acc.y + acc.w);
    }
    __syncthreads();

    // Reduce phase 2: bin b sums its 4 partials.
    if (tid < HB) {
        const int pr = tid >> 1, comp = tid & 1;
        const float* rf = reinterpret_cast<const float*>(racc2);
        float s = 0.0f;
#pragma unroll
        for (int k = 0; k < 4; ++k)
            s += rf[(pr * 4 + k) * 2 + comp];
        g_part[((size_t)nc * SPLITS + split) * HB + tid] = s;
    }
    __syncthreads();

    // Last block per nc reduces + normalizes.
    if (tid == 0) {
        __threadfence();
        unsigned old = atomicAdd(&g_cnt[nc], 1u);
        slast = (old == SPLITS - 1);
    }
    __syncthreads();
    if (!slast) return;
    __threadfence();

    float bsum = 0.0f;
    if (tid < HB) {
        const float* p = g_part + (size_t)nc * SPLITS * HB + tid;
#pragma unroll
        for (int sp = 0; sp < SPLITS; ++sp)
            bsum += p[(size_t)sp * HB];
    }
    float v = (tid < HB) ? bsum : 0.0f;
    float r = v;
#pragma unroll
    for (int o = 16; o; o >>= 1) r += __shfl_xor_sync(0xffffffffu, r, o);
    if (tid == 0)  ws[0] = r;
    if (tid == 32) ws[1] = r;
    __syncthreads();
    float tot = ws[0] + ws[1];

    if (tid < HB)
        out[nc * HB + tid] = v / (tot + 1e-8f);

    if (tid == 0) g_cnt[nc] = 0;   // reset for next graph replay
}

extern "C" void kernel_launch(void* const* d_in, const int* in_sizes, int n_in,
                              void* d_out, int out_size) {
    const float* x        = (const float*)d_in[0];
    const float* bin_vals = (const float*)d_in[1];
    float* out            = (float*)d_out;

    dim3 grid(SPLITS, NC_TOTAL);
    hist_fused_kernel<<<grid, NT>>>(x, bin_vals, out);
}